// round 1
// baseline (speedup 1.0000x reference)
#include <cuda_runtime.h>
#include <math.h>

#define NPTS 262144
#define NLVL 16
#define TSZ  (1u << 19)
#define TMASK (TSZ - 1u)

// 32 MB scratch for hash features (allowed: static __device__ array)
__device__ float g_feat[(size_t)NPTS * 32];

// res = floor(16 * exp(l * ln(32)/15)) evaluated in fp32 (boundary cases verified)
__constant__ int c_res[NLVL] = {16, 20, 25, 32, 40, 50, 64, 80,
                                101, 128, 161, 203, 256, 322, 406, 512};

// ---------------------------------------------------------------------------
// Kernel 1: multires 4-D hash encoding. One thread per point.
// ---------------------------------------------------------------------------
__global__ __launch_bounds__(256) void hash_kernel(
    const float4* __restrict__ xyzt,
    const float* __restrict__ table,
    float* __restrict__ feat)
{
    int n = blockIdx.x * blockDim.x + threadIdx.x;
    if (n >= NPTS) return;
    float4 p = xyzt[n];

    #pragma unroll 1
    for (int l = 0; l < NLVL; l++) {
        float r = (float)c_res[l];
        float px = p.x * r, py = p.y * r, pz = p.z * r, pt = p.w * r;
        float fx = floorf(px), fy = floorf(py), fz = floorf(pz), ft = floorf(pt);
        float wx = px - fx, wy = py - fy, wz = pz - fz, wt = pt - ft;
        unsigned cx = (unsigned)fx, cy = (unsigned)fy, cz = (unsigned)fz, ct = (unsigned)ft;

        // per-dim hash values for offset 0 / 1 (primes: 1, 2654435761, 805459861, 3674653429)
        unsigned hx0 = cx,                     hx1 = cx + 1u;
        unsigned hy0 = cy * 2654435761u,       hy1 = (cy + 1u) * 2654435761u;
        unsigned hz0 = cz * 805459861u,        hz1 = (cz + 1u) * 805459861u;
        unsigned ht0 = ct * 3674653429u,       ht1 = (ct + 1u) * 3674653429u;

        float wx0 = 1.f - wx, wy0 = 1.f - wy, wz0 = 1.f - wz, wt0 = 1.f - wt;

        const float2* tl = (const float2*)table + (size_t)l * TSZ;
        float a0 = 0.f, a1 = 0.f;

        #pragma unroll
        for (int c8 = 0; c8 < 16; c8++) {
            unsigned hxx = (c8 & 1) ? hx1 : hx0;
            unsigned hyy = (c8 & 2) ? hy1 : hy0;
            unsigned hzz = (c8 & 4) ? hz1 : hz0;
            unsigned htt = (c8 & 8) ? ht1 : ht0;
            unsigned idx = (hxx ^ hyy ^ hzz ^ htt) & TMASK;
            float w = ((c8 & 1) ? wx : wx0) * ((c8 & 2) ? wy : wy0) *
                      ((c8 & 4) ? wz : wz0) * ((c8 & 8) ? wt : wt0);
            float2 f = __ldg(&tl[idx]);
            a0 = fmaf(f.x, w, a0);
            a1 = fmaf(f.y, w, a1);
        }
        feat[(size_t)n * 32 + l * 2 + 0] = a0;
        feat[(size_t)n * 32 + l * 2 + 1] = a1;
    }
}

// ---------------------------------------------------------------------------
// Kernel 2: fully-fused MLPs. One thread per point, weights in shared memory.
// ---------------------------------------------------------------------------
// smem layout (floats):
constexpr int OFF_SW0 = 0;                    // 32*64 = 2048
constexpr int OFF_SW1 = OFF_SW0 + 2048;       // 64*64 = 4096
constexpr int OFF_SW2 = OFF_SW1 + 4096;       // 64*16 = 1024
constexpr int OFF_CW0 = OFF_SW2 + 1024;       // 42*64 = 2688
constexpr int OFF_CW1 = OFF_CW0 + 2688;       // 64*64 = 4096
constexpr int OFF_CW2 = OFF_CW1 + 4096;       // 64*4  = 256 (padded from 64*3)
constexpr int SMEM_FLOATS = OFF_CW2 + 256;    // 14208 floats
constexpr int SMEM_BYTES  = SMEM_FLOATS * 4;  // 56832 B

template <int IN, int OUT, bool RELU>
__device__ __forceinline__ void layer(const float* __restrict__ x,
                                      float* __restrict__ y,
                                      const float* __restrict__ ws)
{
    static_assert(OUT % 4 == 0, "OUT must be multiple of 4");
    #pragma unroll
    for (int j = 0; j < OUT; j += 4) {
        float a0 = 0.f, a1 = 0.f, a2 = 0.f, a3 = 0.f;
        #pragma unroll
        for (int i = 0; i < IN; i++) {
            float4 w = *(const float4*)(ws + i * OUT + j);   // broadcast LDS.128
            float xi = x[i];
            a0 = fmaf(xi, w.x, a0);
            a1 = fmaf(xi, w.y, a1);
            a2 = fmaf(xi, w.z, a2);
            a3 = fmaf(xi, w.w, a3);
        }
        if (RELU) {
            a0 = fmaxf(a0, 0.f); a1 = fmaxf(a1, 0.f);
            a2 = fmaxf(a2, 0.f); a3 = fmaxf(a3, 0.f);
        }
        y[j + 0] = a0; y[j + 1] = a1; y[j + 2] = a2; y[j + 3] = a3;
    }
}

__device__ __forceinline__ void loadw(float* dst, const float* __restrict__ src, int n)
{
    for (int k = threadIdx.x; k < n; k += blockDim.x) dst[k] = src[k];
}

__global__ __launch_bounds__(128) void mlp_kernel(
    const float* __restrict__ feat,
    const float* __restrict__ dirs,
    const float* __restrict__ sw0, const float* __restrict__ sw1,
    const float* __restrict__ sw2, const float* __restrict__ cw0,
    const float* __restrict__ cw1, const float* __restrict__ cw2,
    float* __restrict__ out)
{
    extern __shared__ float s[];
    loadw(s + OFF_SW0, sw0, 2048);
    loadw(s + OFF_SW1, sw1, 4096);
    loadw(s + OFF_SW2, sw2, 1024);
    loadw(s + OFF_CW0, cw0, 2688);
    loadw(s + OFF_CW1, cw1, 4096);
    // cw2 is 64x3 -> pad to 64x4 columns
    for (int k = threadIdx.x; k < 256; k += blockDim.x) {
        int i = k >> 2, j = k & 3;
        s[OFF_CW2 + k] = (j < 3) ? cw2[i * 3 + j] : 0.f;
    }
    __syncthreads();

    int n = blockIdx.x * blockDim.x + threadIdx.x;
    if (n >= NPTS) return;

    // load 32 hash features
    float x0[32];
    const float4* fp = (const float4*)(feat + (size_t)n * 32);
    #pragma unroll
    for (int q = 0; q < 8; q++) {
        float4 v = fp[q];
        x0[q * 4 + 0] = v.x; x0[q * 4 + 1] = v.y;
        x0[q * 4 + 2] = v.z; x0[q * 4 + 3] = v.w;
    }

    // sigma net: 32 -> 64 -> 64 -> 16
    float a[64];
    layer<32, 64, true>(x0, a, s + OFF_SW0);
    float b[64];
    layer<64, 64, true>(a, b, s + OFF_SW1);
    float h[16];
    layer<64, 16, false>(b, h, s + OFF_SW2);

    float sigma = h[0];

    // color input: [dirs(3), sin(12: f-major,c-inner), cos(12), geo(15)]
    float cin[42];
    float dd[3];
    dd[0] = dirs[(size_t)n * 3 + 0];
    dd[1] = dirs[(size_t)n * 3 + 1];
    dd[2] = dirs[(size_t)n * 3 + 2];
    cin[0] = dd[0]; cin[1] = dd[1]; cin[2] = dd[2];
    #pragma unroll
    for (int f = 0; f < 4; f++) {
        float fr = (float)(1 << f);
        #pragma unroll
        for (int c = 0; c < 3; c++) {
            float sv, cv;
            sincosf(dd[c] * fr, &sv, &cv);
            cin[3 + f * 3 + c]  = sv;
            cin[15 + f * 3 + c] = cv;
        }
    }
    #pragma unroll
    for (int k = 0; k < 15; k++) cin[27 + k] = h[1 + k];

    // color net: 42 -> 64 -> 64 -> 3(+pad)
    float c1[64];
    layer<42, 64, true>(cin, c1, s + OFF_CW0);
    float c2[64];
    layer<64, 64, true>(c1, c2, s + OFF_CW1);
    float rgb[4];
    layer<64, 4, false>(c2, rgb, s + OFF_CW2);

    // outputs: sigma [0:N), rgbs [N : N+3N) row-major
    out[n] = sigma;
    float r0 = 1.f / (1.f + __expf(-rgb[0]));
    float r1 = 1.f / (1.f + __expf(-rgb[1]));
    float r2 = 1.f / (1.f + __expf(-rgb[2]));
    out[(size_t)NPTS + (size_t)n * 3 + 0] = r0;
    out[(size_t)NPTS + (size_t)n * 3 + 1] = r1;
    out[(size_t)NPTS + (size_t)n * 3 + 2] = r2;
}

// ---------------------------------------------------------------------------
// launch
// ---------------------------------------------------------------------------
extern "C" void kernel_launch(void* const* d_in, const int* in_sizes, int n_in,
                              void* d_out, int out_size)
{
    const float4* xyzt  = (const float4*)d_in[0];
    const float*  dirs  = (const float*)d_in[1];
    const float*  table = (const float*)d_in[2];
    const float*  sw0   = (const float*)d_in[3];
    const float*  sw1   = (const float*)d_in[4];
    const float*  sw2   = (const float*)d_in[5];
    const float*  cw0   = (const float*)d_in[6];
    const float*  cw1   = (const float*)d_in[7];
    const float*  cw2   = (const float*)d_in[8];
    float* out = (float*)d_out;

    cudaFuncSetAttribute(mlp_kernel, cudaFuncAttributeMaxDynamicSharedMemorySize,
                         SMEM_BYTES);

    float* feat;
    cudaGetSymbolAddress((void**)&feat, g_feat);

    hash_kernel<<<NPTS / 256, 256>>>(xyzt, table, feat);
    mlp_kernel<<<NPTS / 128, 128, SMEM_BYTES>>>(feat, dirs, sw0, sw1, sw2,
                                                cw0, cw1, cw2, out);
}

// round 2
// speedup vs baseline: 1.1743x; 1.1743x over previous
#include <cuda_runtime.h>
#include <math.h>

#define NPTS 262144
#define NLVL 16
#define TSZ  (1u << 19)
#define TMASK (TSZ - 1u)

// transposed hash features: feat_t[i][n], i in [0,32)
__device__ float g_feat[(size_t)32 * NPTS];

__constant__ int c_res[NLVL] = {16, 20, 25, 32, 40, 50, 64, 80,
                                101, 128, 161, 203, 256, 322, 406, 512};

// ---------------------------------------------------------------------------
// Kernel 1: multires 4-D hash encoding. One thread per point.
// When cx is even, both x-corners live in one aligned float4 -> one LDG.128.
// ---------------------------------------------------------------------------
__global__ __launch_bounds__(256) void hash_kernel(
    const float4* __restrict__ xyzt,
    const float* __restrict__ table,
    float* __restrict__ feat)
{
    int n = blockIdx.x * blockDim.x + threadIdx.x;
    float4 p = xyzt[n];

    #pragma unroll 1
    for (int l = 0; l < NLVL; l++) {
        float r = (float)c_res[l];
        float px = p.x * r, py = p.y * r, pz = p.z * r, pt = p.w * r;
        float fx = floorf(px), fy = floorf(py), fz = floorf(pz), ft = floorf(pt);
        float wx = px - fx, wy = py - fy, wz = pz - fz, wt = pt - ft;
        unsigned cx = (unsigned)fx, cy = (unsigned)fy, cz = (unsigned)fz, ct = (unsigned)ft;

        unsigned hx0 = cx,               hx1 = cx + 1u;
        unsigned hy0 = cy * 2654435761u, hy1 = (cy + 1u) * 2654435761u;
        unsigned hz0 = cz * 805459861u,  hz1 = (cz + 1u) * 805459861u;
        unsigned ht0 = ct * 3674653429u, ht1 = (ct + 1u) * 3674653429u;

        float wx0 = 1.f - wx, wy0 = 1.f - wy, wz0 = 1.f - wz, wt0 = 1.f - wt;

        const float2* tl = (const float2*)table + (size_t)l * TSZ;
        float a0 = 0.f, a1 = 0.f;

        if ((cx & 1u) == 0u) {
            // paired path: idx1 = idx0 ^ 1 -> one aligned float4 per yzt-corner
            const float4* t4 = (const float4*)tl;
            #pragma unroll
            for (int c8 = 0; c8 < 8; c8++) {
                unsigned hyy = (c8 & 1) ? hy1 : hy0;
                unsigned hzz = (c8 & 2) ? hz1 : hz0;
                unsigned htt = (c8 & 4) ? ht1 : ht0;
                unsigned idx0 = (hx0 ^ hyy ^ hzz ^ htt) & TMASK;
                float wyzt = ((c8 & 1) ? wy : wy0) * ((c8 & 2) ? wz : wz0) *
                             ((c8 & 4) ? wt : wt0);
                float w0 = wx0 * wyzt, w1 = wx * wyzt;
                float4 v = __ldg(&t4[idx0 >> 1]);
                bool hi = (idx0 & 1u);
                float f0x = hi ? v.z : v.x, f0y = hi ? v.w : v.y;
                float f1x = hi ? v.x : v.z, f1y = hi ? v.y : v.w;
                a0 = fmaf(f0x, w0, a0); a0 = fmaf(f1x, w1, a0);
                a1 = fmaf(f0y, w0, a1); a1 = fmaf(f1y, w1, a1);
            }
        } else {
            #pragma unroll
            for (int c8 = 0; c8 < 16; c8++) {
                unsigned hxx = (c8 & 1) ? hx1 : hx0;
                unsigned hyy = (c8 & 2) ? hy1 : hy0;
                unsigned hzz = (c8 & 4) ? hz1 : hz0;
                unsigned htt = (c8 & 8) ? ht1 : ht0;
                unsigned idx = (hxx ^ hyy ^ hzz ^ htt) & TMASK;
                float w = ((c8 & 1) ? wx : wx0) * ((c8 & 2) ? wy : wy0) *
                          ((c8 & 4) ? wz : wz0) * ((c8 & 8) ? wt : wt0);
                float2 f = __ldg(&tl[idx]);
                a0 = fmaf(f.x, w, a0);
                a1 = fmaf(f.y, w, a1);
            }
        }
        // transposed, coalesced store
        feat[(size_t)(l * 2 + 0) * NPTS + n] = a0;
        feat[(size_t)(l * 2 + 1) * NPTS + n] = a1;
    }
}

// ---------------------------------------------------------------------------
// Kernel 2: block-cooperative GEMM MLP. 128 points/block, 256 threads.
// Thread tile: 8 points x 4 neurons.
// ---------------------------------------------------------------------------
constexpr int BP = 128;          // points per block
constexpr int S  = 132;          // activation row stride (floats)

// weight smem offsets (floats)
constexpr int OFF_SW0 = 0;                    // 32*64
constexpr int OFF_SW1 = OFF_SW0 + 2048;       // 64*64
constexpr int OFF_SW2 = OFF_SW1 + 4096;       // 64*16
constexpr int OFF_CW0 = OFF_SW2 + 1024;       // 42*64
constexpr int OFF_CW1 = OFF_CW0 + 2688;       // 64*64
constexpr int OFF_CW2 = OFF_CW1 + 4096;       // 64*4 padded
constexpr int W_FLOATS = OFF_CW2 + 256;       // 14208
constexpr int OFF_B0 = W_FLOATS;              // 64*S
constexpr int OFF_B1 = OFF_B0 + 64 * S;
constexpr int SMEM_FLOATS = OFF_B1 + 64 * S;  // 14208 + 16896 = 31104
constexpr int SMEM_BYTES = SMEM_FLOATS * 4;   // 124416

// OUT=64 GEMM step: y[64][S] = act(w[IN][64]^T . x[IN][S])
template <int IN, bool RELU, int UNROLL>
__device__ __forceinline__ void gemm64(const float* __restrict__ xb,
                                       float* __restrict__ yb,
                                       const float* __restrict__ w,
                                       int pg, int ng)
{
    float acc[4][8];
    #pragma unroll
    for (int n = 0; n < 4; n++)
        #pragma unroll
        for (int q = 0; q < 8; q++) acc[n][q] = 0.f;

    const float* xr = xb + pg * 8;
    const float* wr = w + ng * 4;
    #pragma unroll UNROLL
    for (int i = 0; i < IN; i++) {
        float4 xa = *(const float4*)(xr + i * S);
        float4 xc = *(const float4*)(xr + i * S + 4);
        float4 wv = *(const float4*)(wr + i * 64);
        float xv[8] = {xa.x, xa.y, xa.z, xa.w, xc.x, xc.y, xc.z, xc.w};
        float wn[4] = {wv.x, wv.y, wv.z, wv.w};
        #pragma unroll
        for (int n = 0; n < 4; n++)
            #pragma unroll
            for (int q = 0; q < 8; q++)
                acc[n][q] = fmaf(wn[n], xv[q], acc[n][q]);
    }
    #pragma unroll
    for (int n = 0; n < 4; n++) {
        #pragma unroll
        for (int q = 0; q < 8; q++)
            if (RELU) acc[n][q] = fmaxf(acc[n][q], 0.f);
        float* yr = yb + (ng * 4 + n) * S + pg * 8;
        *(float4*)(yr)     = make_float4(acc[n][0], acc[n][1], acc[n][2], acc[n][3]);
        *(float4*)(yr + 4) = make_float4(acc[n][4], acc[n][5], acc[n][6], acc[n][7]);
    }
}

// OUT=16 GEMM step (sw2): one neuron per thread
__device__ __forceinline__ void gemm16(const float* __restrict__ xb,
                                       float* __restrict__ yb,
                                       const float* __restrict__ w,
                                       int pg, int ng)
{
    float acc[8];
    #pragma unroll
    for (int q = 0; q < 8; q++) acc[q] = 0.f;
    const float* xr = xb + pg * 8;
    #pragma unroll 8
    for (int i = 0; i < 64; i++) {
        float4 xa = *(const float4*)(xr + i * S);
        float4 xc = *(const float4*)(xr + i * S + 4);
        float wv = w[i * 16 + ng];
        acc[0] = fmaf(wv, xa.x, acc[0]); acc[1] = fmaf(wv, xa.y, acc[1]);
        acc[2] = fmaf(wv, xa.z, acc[2]); acc[3] = fmaf(wv, xa.w, acc[3]);
        acc[4] = fmaf(wv, xc.x, acc[4]); acc[5] = fmaf(wv, xc.y, acc[5]);
        acc[6] = fmaf(wv, xc.z, acc[6]); acc[7] = fmaf(wv, xc.w, acc[7]);
    }
    float* yr = yb + ng * S + pg * 8;
    *(float4*)(yr)     = make_float4(acc[0], acc[1], acc[2], acc[3]);
    *(float4*)(yr + 4) = make_float4(acc[4], acc[5], acc[6], acc[7]);
}

__device__ __forceinline__ void loadw4(float* dst, const float* __restrict__ src,
                                       int n4, int tid)
{
    for (int k = tid; k < n4; k += 256)
        ((float4*)dst)[k] = ((const float4*)src)[k];
}

__global__ __launch_bounds__(256) void mlp_kernel(
    const float* __restrict__ feat,
    const float* __restrict__ dirs,
    const float* __restrict__ sw0, const float* __restrict__ sw1,
    const float* __restrict__ sw2, const float* __restrict__ cw0,
    const float* __restrict__ cw1, const float* __restrict__ cw2,
    float* __restrict__ out)
{
    extern __shared__ float s[];
    int tid = threadIdx.x;
    int gbase = blockIdx.x * BP;
    int pg = tid & 15, ng = tid >> 4;

    // stage weights
    loadw4(s + OFF_SW0, sw0, 2048 / 4, tid);
    loadw4(s + OFF_SW1, sw1, 4096 / 4, tid);
    loadw4(s + OFF_SW2, sw2, 1024 / 4, tid);
    loadw4(s + OFF_CW0, cw0, 2688 / 4, tid);
    loadw4(s + OFF_CW1, cw1, 4096 / 4, tid);
    if (tid < 256) {
        int i = tid >> 2, j = tid & 3;
        s[OFF_CW2 + tid] = (j < 3) ? cw2[i * 3 + j] : 0.f;
    }
    // stage input features (transposed global layout -> rows)
    #pragma unroll
    for (int r = 0; r < 4; r++) {
        int idx = tid + r * 256;          // 1024 float4s: 32 rows x 32 float4
        int i = idx >> 5, q = idx & 31;
        *(float4*)(s + OFF_B0 + i * S + q * 4) =
            *(const float4*)(feat + (size_t)i * NPTS + gbase + q * 4);
    }
    __syncthreads();

    // sigma net
    gemm64<32, true, 32>(s + OFF_B0, s + OFF_B1, s + OFF_SW0, pg, ng);
    __syncthreads();
    gemm64<64, true, 8>(s + OFF_B1, s + OFF_B0, s + OFF_SW1, pg, ng);
    __syncthreads();
    gemm16(s + OFF_B0, s + OFF_B1, s + OFF_SW2, pg, ng);   // h -> B1 rows 0..15
    __syncthreads();

    // color input assembly: B0 rows 0..41; also emit sigma
    if (tid < BP) {
        int p = tid;
        int gn = gbase + p;
        float d0 = dirs[(size_t)gn * 3 + 0];
        float d1 = dirs[(size_t)gn * 3 + 1];
        float d2 = dirs[(size_t)gn * 3 + 2];
        s[OFF_B0 + 0 * S + p] = d0;
        s[OFF_B0 + 1 * S + p] = d1;
        s[OFF_B0 + 2 * S + p] = d2;
        float dd[3] = {d0, d1, d2};
        #pragma unroll
        for (int f = 0; f < 4; f++) {
            float fr = (float)(1 << f);
            #pragma unroll
            for (int c = 0; c < 3; c++) {
                float sv, cv;
                sincosf(dd[c] * fr, &sv, &cv);
                s[OFF_B0 + (3 + f * 3 + c) * S + p] = sv;
                s[OFF_B0 + (15 + f * 3 + c) * S + p] = cv;
            }
        }
        #pragma unroll
        for (int k = 0; k < 15; k++)
            s[OFF_B0 + (27 + k) * S + p] = s[OFF_B1 + (1 + k) * S + p];
        out[gn] = s[OFF_B1 + 0 * S + p];   // sigma
    }
    __syncthreads();

    // color net
    gemm64<42, true, 42>(s + OFF_B0, s + OFF_B1, s + OFF_CW0, pg, ng);
    __syncthreads();
    gemm64<64, true, 8>(s + OFF_B1, s + OFF_B0, s + OFF_CW1, pg, ng);
    __syncthreads();

    // final 64 -> 3 + sigmoid, per point
    if (tid < BP) {
        int p = tid;
        int gn = gbase + p;
        float r0 = 0.f, r1 = 0.f, r2 = 0.f;
        #pragma unroll 8
        for (int i = 0; i < 64; i++) {
            float xv = s[OFF_B0 + i * S + p];
            float4 wv = *(const float4*)(s + OFF_CW2 + i * 4);
            r0 = fmaf(xv, wv.x, r0);
            r1 = fmaf(xv, wv.y, r1);
            r2 = fmaf(xv, wv.z, r2);
        }
        out[(size_t)NPTS + (size_t)gn * 3 + 0] = 1.f / (1.f + __expf(-r0));
        out[(size_t)NPTS + (size_t)gn * 3 + 1] = 1.f / (1.f + __expf(-r1));
        out[(size_t)NPTS + (size_t)gn * 3 + 2] = 1.f / (1.f + __expf(-r2));
    }
}

// ---------------------------------------------------------------------------
extern "C" void kernel_launch(void* const* d_in, const int* in_sizes, int n_in,
                              void* d_out, int out_size)
{
    const float4* xyzt  = (const float4*)d_in[0];
    const float*  dirs  = (const float*)d_in[1];
    const float*  table = (const float*)d_in[2];
    const float*  sw0   = (const float*)d_in[3];
    const float*  sw1   = (const float*)d_in[4];
    const float*  sw2   = (const float*)d_in[5];
    const float*  cw0   = (const float*)d_in[6];
    const float*  cw1   = (const float*)d_in[7];
    const float*  cw2   = (const float*)d_in[8];
    float* out = (float*)d_out;

    static int attr_set = 0;
    cudaFuncSetAttribute(mlp_kernel, cudaFuncAttributeMaxDynamicSharedMemorySize,
                         SMEM_BYTES);
    (void)attr_set;

    float* feat;
    cudaGetSymbolAddress((void**)&feat, g_feat);

    hash_kernel<<<NPTS / 256, 256>>>(xyzt, table, feat);
    mlp_kernel<<<NPTS / BP, 256, SMEM_BYTES>>>(feat, dirs, sw0, sw1, sw2,
                                               cw0, cw1, cw2, out);
}

// round 3
// speedup vs baseline: 1.2642x; 1.0765x over previous
#include <cuda_runtime.h>
#include <math.h>

#define NPTS 262144
#define NLVL 16
#define TSZ  (1u << 19)
#define TMASK (TSZ - 1u)

// ---------------------------------------------------------------------------
// Weights in constant memory (warp-uniform reads -> uniform datapath, no L1tex)
// ---------------------------------------------------------------------------
constexpr int OFF_SW0 = 0;            // 32*64
constexpr int OFF_SW1 = 2048;         // 64*64
constexpr int OFF_SW2 = 6144;         // 64*16
constexpr int OFF_CW0 = 7168;         // 42*64
constexpr int OFF_CW1 = 9856;         // 64*64
constexpr int OFF_CW2 = 13952;        // 64*3
constexpr int W_TOTAL = 14144;
__constant__ float c_w[W_TOTAL];

__constant__ int c_res[NLVL] = {16, 20, 25, 32, 40, 50, 64, 80,
                                101, 128, 161, 203, 256, 322, 406, 512};

// smem: two activation buffers, 64 rows x S floats
constexpr int BP = 128;
constexpr int S  = 132;
constexpr int OFF_B0 = 0;
constexpr int OFF_B1 = 64 * S;
constexpr int SMEM_FLOATS = 2 * 64 * S;          // 16896
constexpr int SMEM_BYTES  = SMEM_FLOATS * 4;     // 67584

// ---------------------------------------------------------------------------
// GEMM step: y[64][S] = act(W[IN][64]^T x[IN][S]).
// warp -> 8 neurons (uniform cmem weights), lane -> 4 points.
// ---------------------------------------------------------------------------
template <int IN, bool RELU>
__device__ __forceinline__ void gemmC(const float* __restrict__ xb,
                                      float* __restrict__ yb,
                                      int woff, int warp, int lane)
{
    float acc[8][4];
    #pragma unroll
    for (int n = 0; n < 8; n++)
        #pragma unroll
        for (int q = 0; q < 4; q++) acc[n][q] = 0.f;

    const float* xr = xb + lane * 4;
    const int wb = woff + warp * 8;
    #pragma unroll 4
    for (int i = 0; i < IN; i++) {
        float4 xv = *(const float4*)(xr + i * S);
        #pragma unroll
        for (int n = 0; n < 8; n++) {
            float w = c_w[wb + i * 64 + n];          // warp-uniform -> LDCU
            acc[n][0] = fmaf(w, xv.x, acc[n][0]);
            acc[n][1] = fmaf(w, xv.y, acc[n][1]);
            acc[n][2] = fmaf(w, xv.z, acc[n][2]);
            acc[n][3] = fmaf(w, xv.w, acc[n][3]);
        }
    }
    #pragma unroll
    for (int n = 0; n < 8; n++) {
        float4 v;
        if (RELU) {
            v = make_float4(fmaxf(acc[n][0], 0.f), fmaxf(acc[n][1], 0.f),
                            fmaxf(acc[n][2], 0.f), fmaxf(acc[n][3], 0.f));
        } else {
            v = make_float4(acc[n][0], acc[n][1], acc[n][2], acc[n][3]);
        }
        *(float4*)(yb + (warp * 8 + n) * S + lane * 4) = v;
    }
}

// sw2 GEMM (64 -> 16): warp -> 2 neurons
__device__ __forceinline__ void gemm16C(const float* __restrict__ xb,
                                        float* __restrict__ yb,
                                        int warp, int lane)
{
    float acc[2][4];
    #pragma unroll
    for (int n = 0; n < 2; n++)
        #pragma unroll
        for (int q = 0; q < 4; q++) acc[n][q] = 0.f;

    const float* xr = xb + lane * 4;
    const int wb = OFF_SW2 + warp * 2;
    #pragma unroll 8
    for (int i = 0; i < 64; i++) {
        float4 xv = *(const float4*)(xr + i * S);
        #pragma unroll
        for (int n = 0; n < 2; n++) {
            float w = c_w[wb + i * 16 + n];
            acc[n][0] = fmaf(w, xv.x, acc[n][0]);
            acc[n][1] = fmaf(w, xv.y, acc[n][1]);
            acc[n][2] = fmaf(w, xv.z, acc[n][2]);
            acc[n][3] = fmaf(w, xv.w, acc[n][3]);
        }
    }
    #pragma unroll
    for (int n = 0; n < 2; n++)
        *(float4*)(yb + (warp * 2 + n) * S + lane * 4) =
            make_float4(acc[n][0], acc[n][1], acc[n][2], acc[n][3]);
}

// ---------------------------------------------------------------------------
// Fused kernel: hash encode (-> smem) then MLPs. 128 points / block.
// ---------------------------------------------------------------------------
__global__ __launch_bounds__(256, 3) void fused_kernel(
    const float* __restrict__ xyzt,
    const float* __restrict__ dirs,
    const float* __restrict__ table,
    float* __restrict__ out)
{
    extern __shared__ float s[];
    const int tid = threadIdx.x;
    const int warp = tid >> 5, lane = tid & 31;
    const int gbase = blockIdx.x * BP;

    // ---- stage xyzt (128 float4 = 512 floats) into B1 ----
    #pragma unroll
    for (int t = tid; t < 512; t += 256)
        s[OFF_B1 + t] = xyzt[(size_t)gbase * 4 + t];
    __syncthreads();

    // ---- hash phase: each thread = one point, 8 levels ----
    {
        const int p = tid & 127;
        const int lh = tid >> 7;                     // 0 or 1 (warp-uniform)
        float4 pt = *(const float4*)(s + OFF_B1 + p * 4);

        #pragma unroll 1
        for (int k = 0; k < 8; k++) {
            const int l = 2 * k + lh;
            float r = (float)c_res[l];
            float px = pt.x * r, py = pt.y * r, pz = pt.z * r, pw = pt.w * r;
            float fx = floorf(px), fy = floorf(py), fz = floorf(pz), ft = floorf(pw);
            float wx = px - fx, wy = py - fy, wz = pz - fz, wt = pw - ft;
            unsigned cx = (unsigned)fx, cy = (unsigned)fy,
                     cz = (unsigned)fz, ct = (unsigned)ft;

            unsigned hx0 = cx,               hx1 = cx + 1u;
            unsigned hy0 = cy * 2654435761u, hy1 = (cy + 1u) * 2654435761u;
            unsigned hz0 = cz * 805459861u,  hz1 = (cz + 1u) * 805459861u;
            unsigned ht0 = ct * 3674653429u, ht1 = (ct + 1u) * 3674653429u;

            float wx0 = 1.f - wx, wy0 = 1.f - wy, wz0 = 1.f - wz, wt0 = 1.f - wt;

            const float2* tl = (const float2*)table + (size_t)l * TSZ;
            float a0 = 0.f, a1 = 0.f;

            if ((cx & 1u) == 0u) {
                const float4* t4 = (const float4*)tl;
                #pragma unroll
                for (int c8 = 0; c8 < 8; c8++) {
                    unsigned hyy = (c8 & 1) ? hy1 : hy0;
                    unsigned hzz = (c8 & 2) ? hz1 : hz0;
                    unsigned htt = (c8 & 4) ? ht1 : ht0;
                    unsigned idx0 = (hx0 ^ hyy ^ hzz ^ htt) & TMASK;
                    float wyzt = ((c8 & 1) ? wy : wy0) * ((c8 & 2) ? wz : wz0) *
                                 ((c8 & 4) ? wt : wt0);
                    float w0 = wx0 * wyzt, w1 = wx * wyzt;
                    float4 v = __ldg(&t4[idx0 >> 1]);
                    bool hi = (idx0 & 1u);
                    float f0x = hi ? v.z : v.x, f0y = hi ? v.w : v.y;
                    float f1x = hi ? v.x : v.z, f1y = hi ? v.y : v.w;
                    a0 = fmaf(f0x, w0, a0); a0 = fmaf(f1x, w1, a0);
                    a1 = fmaf(f0y, w0, a1); a1 = fmaf(f1y, w1, a1);
                }
            } else {
                #pragma unroll
                for (int c8 = 0; c8 < 16; c8++) {
                    unsigned hxx = (c8 & 1) ? hx1 : hx0;
                    unsigned hyy = (c8 & 2) ? hy1 : hy0;
                    unsigned hzz = (c8 & 4) ? hz1 : hz0;
                    unsigned htt = (c8 & 8) ? ht1 : ht0;
                    unsigned idx = (hxx ^ hyy ^ hzz ^ htt) & TMASK;
                    float w = ((c8 & 1) ? wx : wx0) * ((c8 & 2) ? wy : wy0) *
                              ((c8 & 4) ? wz : wz0) * ((c8 & 8) ? wt : wt0);
                    float2 f = __ldg(&tl[idx]);
                    a0 = fmaf(f.x, w, a0);
                    a1 = fmaf(f.y, w, a1);
                }
            }
            s[OFF_B0 + (2 * l + 0) * S + p] = a0;
            s[OFF_B0 + (2 * l + 1) * S + p] = a1;
        }
    }
    __syncthreads();

    // ---- sigma net ----
    gemmC<32, true>(s + OFF_B0, s + OFF_B1, OFF_SW0, warp, lane);
    __syncthreads();
    gemmC<64, true>(s + OFF_B1, s + OFF_B0, OFF_SW1, warp, lane);
    __syncthreads();
    gemm16C(s + OFF_B0, s + OFF_B1, warp, lane);       // h -> B1 rows 0..15
    __syncthreads();

    // ---- color input assembly + sigma output ----
    if (tid < BP) {
        const int p = tid;
        const int gn = gbase + p;
        float d0 = dirs[(size_t)gn * 3 + 0];
        float d1 = dirs[(size_t)gn * 3 + 1];
        float d2 = dirs[(size_t)gn * 3 + 2];
        s[OFF_B0 + 0 * S + p] = d0;
        s[OFF_B0 + 1 * S + p] = d1;
        s[OFF_B0 + 2 * S + p] = d2;
        float dd[3] = {d0, d1, d2};
        #pragma unroll
        for (int f = 0; f < 4; f++) {
            float fr = (float)(1 << f);
            #pragma unroll
            for (int c = 0; c < 3; c++) {
                float sv, cv;
                sincosf(dd[c] * fr, &sv, &cv);
                s[OFF_B0 + (3 + f * 3 + c) * S + p]  = sv;
                s[OFF_B0 + (15 + f * 3 + c) * S + p] = cv;
            }
        }
        #pragma unroll
        for (int k = 0; k < 15; k++)
            s[OFF_B0 + (27 + k) * S + p] = s[OFF_B1 + (1 + k) * S + p];
        out[gn] = s[OFF_B1 + 0 * S + p];               // sigma
    }
    __syncthreads();

    // ---- color net ----
    gemmC<42, true>(s + OFF_B0, s + OFF_B1, OFF_CW0, warp, lane);
    __syncthreads();
    gemmC<64, true>(s + OFF_B1, s + OFF_B0, OFF_CW1, warp, lane);
    __syncthreads();

    // ---- final 64 -> 3 + sigmoid ----
    if (tid < BP) {
        const int p = tid;
        const int gn = gbase + p;
        float r0 = 0.f, r1 = 0.f, r2 = 0.f;
        #pragma unroll 8
        for (int i = 0; i < 64; i++) {
            float xv = s[OFF_B0 + i * S + p];
            r0 = fmaf(xv, c_w[OFF_CW2 + i * 3 + 0], r0);
            r1 = fmaf(xv, c_w[OFF_CW2 + i * 3 + 1], r1);
            r2 = fmaf(xv, c_w[OFF_CW2 + i * 3 + 2], r2);
        }
        out[(size_t)NPTS + (size_t)gn * 3 + 0] = 1.f / (1.f + __expf(-r0));
        out[(size_t)NPTS + (size_t)gn * 3 + 1] = 1.f / (1.f + __expf(-r1));
        out[(size_t)NPTS + (size_t)gn * 3 + 2] = 1.f / (1.f + __expf(-r2));
    }
}

// ---------------------------------------------------------------------------
extern "C" void kernel_launch(void* const* d_in, const int* in_sizes, int n_in,
                              void* d_out, int out_size)
{
    const float* xyzt  = (const float*)d_in[0];
    const float* dirs  = (const float*)d_in[1];
    const float* table = (const float*)d_in[2];

    // stage weights into constant memory (async D2D, graph-capturable)
    cudaMemcpyToSymbolAsync(c_w, d_in[3], 2048 * 4, OFF_SW0 * 4,
                            cudaMemcpyDeviceToDevice);
    cudaMemcpyToSymbolAsync(c_w, d_in[4], 4096 * 4, OFF_SW1 * 4,
                            cudaMemcpyDeviceToDevice);
    cudaMemcpyToSymbolAsync(c_w, d_in[5], 1024 * 4, OFF_SW2 * 4,
                            cudaMemcpyDeviceToDevice);
    cudaMemcpyToSymbolAsync(c_w, d_in[6], 2688 * 4, OFF_CW0 * 4,
                            cudaMemcpyDeviceToDevice);
    cudaMemcpyToSymbolAsync(c_w, d_in[7], 4096 * 4, OFF_CW1 * 4,
                            cudaMemcpyDeviceToDevice);
    cudaMemcpyToSymbolAsync(c_w, d_in[8], 192 * 4, OFF_CW2 * 4,
                            cudaMemcpyDeviceToDevice);

    cudaFuncSetAttribute(fused_kernel, cudaFuncAttributeMaxDynamicSharedMemorySize,
                         SMEM_BYTES);

    fused_kernel<<<NPTS / BP, 256, SMEM_BYTES>>>(xyzt, dirs, table, (float*)d_out);
}

// round 4
// speedup vs baseline: 1.4461x; 1.1438x over previous
#include <cuda_runtime.h>
#include <math.h>

#define NPTS 262144
#define NLVL 16
#define TSZ  (1u << 19)
#define TMASK (TSZ - 1u)

typedef unsigned long long u64t;

// packed fp32x2 helpers (SASS FFMA2 — only reachable via PTX)
__device__ __forceinline__ u64t pk2(float a, float b) {
    u64t r; asm("mov.b64 %0,{%1,%2};" : "=l"(r) : "f"(a), "f"(b)); return r;
}
__device__ __forceinline__ void upk2(u64t v, float& a, float& b) {
    asm("mov.b64 {%0,%1},%2;" : "=f"(a), "=f"(b) : "l"(v));
}
__device__ __forceinline__ void fma2(u64t& d, u64t a, u64t b) {
    asm("fma.rn.f32x2 %0,%1,%2,%0;" : "+l"(d) : "l"(a), "l"(b));
}

// ---------------------------------------------------------------------------
// Weights in constant memory
// ---------------------------------------------------------------------------
constexpr int OFF_SW0 = 0;            // 32*64
constexpr int OFF_SW1 = 2048;         // 64*64
constexpr int OFF_SW2 = 6144;         // 64*16
constexpr int OFF_CW0 = 7168;         // 42*64
constexpr int OFF_CW1 = 9856;         // 64*64
constexpr int OFF_CW2 = 13952;        // 64*3
constexpr int W_TOTAL = 14144;
__constant__ float c_w[W_TOTAL];

__constant__ int c_res[NLVL] = {16, 20, 25, 32, 40, 50, 64, 80,
                                101, 128, 161, 203, 256, 322, 406, 512};

constexpr int BP = 128;
constexpr int S  = 132;
constexpr int OFF_B0 = 0;
constexpr int OFF_B1 = 64 * S;
constexpr int SMEM_FLOATS = 2 * 64 * S;          // 16896
constexpr int SMEM_BYTES  = SMEM_FLOATS * 4;     // 67584

// ---------------------------------------------------------------------------
// GEMM step with FFMA2: y[64][S] = act(W[IN][64]^T x[IN][S]).
// warp -> 8 neurons, lane -> 4 points (2 f32x2 pairs).
// ---------------------------------------------------------------------------
template <int IN, bool RELU>
__device__ __forceinline__ void gemmC(const float* __restrict__ xb,
                                      float* __restrict__ yb,
                                      int woff, int warp, int lane)
{
    u64t acc[8][2];
    #pragma unroll
    for (int n = 0; n < 8; n++) { acc[n][0] = 0ull; acc[n][1] = 0ull; }

    const float* xr = xb + lane * 4;
    const int wb = woff + warp * 8;
    #pragma unroll 8
    for (int i = 0; i < IN; i++) {
        float4 xv = *(const float4*)(xr + i * S);
        u64t x01 = pk2(xv.x, xv.y);
        u64t x23 = pk2(xv.z, xv.w);
        float4 w0 = *(const float4*)(c_w + wb + i * 64);
        float4 w1 = *(const float4*)(c_w + wb + i * 64 + 4);
        u64t wd;
        wd = pk2(w0.x, w0.x); fma2(acc[0][0], x01, wd); fma2(acc[0][1], x23, wd);
        wd = pk2(w0.y, w0.y); fma2(acc[1][0], x01, wd); fma2(acc[1][1], x23, wd);
        wd = pk2(w0.z, w0.z); fma2(acc[2][0], x01, wd); fma2(acc[2][1], x23, wd);
        wd = pk2(w0.w, w0.w); fma2(acc[3][0], x01, wd); fma2(acc[3][1], x23, wd);
        wd = pk2(w1.x, w1.x); fma2(acc[4][0], x01, wd); fma2(acc[4][1], x23, wd);
        wd = pk2(w1.y, w1.y); fma2(acc[5][0], x01, wd); fma2(acc[5][1], x23, wd);
        wd = pk2(w1.z, w1.z); fma2(acc[6][0], x01, wd); fma2(acc[6][1], x23, wd);
        wd = pk2(w1.w, w1.w); fma2(acc[7][0], x01, wd); fma2(acc[7][1], x23, wd);
    }
    #pragma unroll
    for (int n = 0; n < 8; n++) {
        float a0, a1, a2, a3;
        upk2(acc[n][0], a0, a1);
        upk2(acc[n][1], a2, a3);
        if (RELU) {
            a0 = fmaxf(a0, 0.f); a1 = fmaxf(a1, 0.f);
            a2 = fmaxf(a2, 0.f); a3 = fmaxf(a3, 0.f);
        }
        *(float4*)(yb + (warp * 8 + n) * S + lane * 4) =
            make_float4(a0, a1, a2, a3);
    }
}

// sw2 GEMM (64 -> 16): warp -> 2 neurons
__device__ __forceinline__ void gemm16C(const float* __restrict__ xb,
                                        float* __restrict__ yb,
                                        int warp, int lane)
{
    u64t acc[2][2];
    acc[0][0] = acc[0][1] = acc[1][0] = acc[1][1] = 0ull;

    const float* xr = xb + lane * 4;
    const int wb = OFF_SW2 + warp * 2;
    #pragma unroll 8
    for (int i = 0; i < 64; i++) {
        float4 xv = *(const float4*)(xr + i * S);
        u64t x01 = pk2(xv.x, xv.y);
        u64t x23 = pk2(xv.z, xv.w);
        float2 wv = *(const float2*)(c_w + wb + i * 16);
        u64t wd;
        wd = pk2(wv.x, wv.x); fma2(acc[0][0], x01, wd); fma2(acc[0][1], x23, wd);
        wd = pk2(wv.y, wv.y); fma2(acc[1][0], x01, wd); fma2(acc[1][1], x23, wd);
    }
    #pragma unroll
    for (int n = 0; n < 2; n++) {
        float a0, a1, a2, a3;
        upk2(acc[n][0], a0, a1);
        upk2(acc[n][1], a2, a3);
        *(float4*)(yb + (warp * 2 + n) * S + lane * 4) =
            make_float4(a0, a1, a2, a3);
    }
}

// ---------------------------------------------------------------------------
// Fused kernel: hash encode (-> smem) then MLPs. 128 points / block.
// ---------------------------------------------------------------------------
__global__ __launch_bounds__(256, 3) void fused_kernel(
    const float* __restrict__ xyzt,
    const float* __restrict__ dirs,
    const float* __restrict__ table,
    float* __restrict__ out)
{
    extern __shared__ float s[];
    const int tid = threadIdx.x;
    const int warp = tid >> 5, lane = tid & 31;
    const int gbase = blockIdx.x * BP;

    // ---- stage xyzt into B1 ----
    #pragma unroll
    for (int t = tid; t < 512; t += 256)
        s[OFF_B1 + t] = xyzt[(size_t)gbase * 4 + t];
    __syncthreads();

    // ---- hash phase: each thread = one point, 8 levels ----
    {
        const int p = tid & 127;
        const int lh = tid >> 7;                     // 0 or 1 (warp-uniform)
        float4 pt = *(const float4*)(s + OFF_B1 + p * 4);

        #pragma unroll 1
        for (int k = 0; k < 8; k++) {
            const int l = 2 * k + lh;
            float r = (float)c_res[l];
            float px = pt.x * r, py = pt.y * r, pz = pt.z * r, pw = pt.w * r;
            float fx = floorf(px), fy = floorf(py), fz = floorf(pz), ft = floorf(pw);
            float wx = px - fx, wy = py - fy, wz = pz - fz, wt = pw - ft;
            unsigned cx = (unsigned)fx, cy = (unsigned)fy,
                     cz = (unsigned)fz, ct = (unsigned)ft;

            unsigned hx0 = cx,               hx1 = cx + 1u;
            unsigned hy0 = cy * 2654435761u, hy1 = (cy + 1u) * 2654435761u;
            unsigned hz0 = cz * 805459861u,  hz1 = (cz + 1u) * 805459861u;
            unsigned ht0 = ct * 3674653429u, ht1 = (ct + 1u) * 3674653429u;

            float wx0 = 1.f - wx, wy0 = 1.f - wy, wz0 = 1.f - wz, wt0 = 1.f - wt;

            const float2* tl = (const float2*)table + (size_t)l * TSZ;
            float a0 = 0.f, a1 = 0.f;

            if ((cx & 1u) == 0u) {
                const float4* t4 = (const float4*)tl;
                #pragma unroll
                for (int c8 = 0; c8 < 8; c8++) {
                    unsigned hyy = (c8 & 1) ? hy1 : hy0;
                    unsigned hzz = (c8 & 2) ? hz1 : hz0;
                    unsigned htt = (c8 & 4) ? ht1 : ht0;
                    unsigned idx0 = (hx0 ^ hyy ^ hzz ^ htt) & TMASK;
                    float wyzt = ((c8 & 1) ? wy : wy0) * ((c8 & 2) ? wz : wz0) *
                                 ((c8 & 4) ? wt : wt0);
                    float w0 = wx0 * wyzt, w1 = wx * wyzt;
                    float4 v = __ldg(&t4[idx0 >> 1]);
                    bool hi = (idx0 & 1u);
                    float f0x = hi ? v.z : v.x, f0y = hi ? v.w : v.y;
                    float f1x = hi ? v.x : v.z, f1y = hi ? v.y : v.w;
                    a0 = fmaf(f0x, w0, a0); a0 = fmaf(f1x, w1, a0);
                    a1 = fmaf(f0y, w0, a1); a1 = fmaf(f1y, w1, a1);
                }
            } else {
                #pragma unroll
                for (int c8 = 0; c8 < 16; c8++) {
                    unsigned hxx = (c8 & 1) ? hx1 : hx0;
                    unsigned hyy = (c8 & 2) ? hy1 : hy0;
                    unsigned hzz = (c8 & 4) ? hz1 : hz0;
                    unsigned htt = (c8 & 8) ? ht1 : ht0;
                    unsigned idx = (hxx ^ hyy ^ hzz ^ htt) & TMASK;
                    float w = ((c8 & 1) ? wx : wx0) * ((c8 & 2) ? wy : wy0) *
                              ((c8 & 4) ? wz : wz0) * ((c8 & 8) ? wt : wt0);
                    float2 f = __ldg(&tl[idx]);
                    a0 = fmaf(f.x, w, a0);
                    a1 = fmaf(f.y, w, a1);
                }
            }
            s[OFF_B0 + (2 * l + 0) * S + p] = a0;
            s[OFF_B0 + (2 * l + 1) * S + p] = a1;
        }
    }
    __syncthreads();

    // ---- sigma net ----
    gemmC<32, true>(s + OFF_B0, s + OFF_B1, OFF_SW0, warp, lane);
    __syncthreads();
    gemmC<64, true>(s + OFF_B1, s + OFF_B0, OFF_SW1, warp, lane);
    __syncthreads();
    gemm16C(s + OFF_B0, s + OFF_B1, warp, lane);       // h -> B1 rows 0..15
    __syncthreads();

    // ---- color input assembly + sigma output ----
    if (tid < BP) {
        const int p = tid;
        const int gn = gbase + p;
        float d0 = dirs[(size_t)gn * 3 + 0];
        float d1 = dirs[(size_t)gn * 3 + 1];
        float d2 = dirs[(size_t)gn * 3 + 2];
        s[OFF_B0 + 0 * S + p] = d0;
        s[OFF_B0 + 1 * S + p] = d1;
        s[OFF_B0 + 2 * S + p] = d2;
        float dd[3] = {d0, d1, d2};
        #pragma unroll
        for (int f = 0; f < 4; f++) {
            float fr = (float)(1 << f);
            #pragma unroll
            for (int c = 0; c < 3; c++) {
                float sv, cv;
                sincosf(dd[c] * fr, &sv, &cv);
                s[OFF_B0 + (3 + f * 3 + c) * S + p]  = sv;
                s[OFF_B0 + (15 + f * 3 + c) * S + p] = cv;
            }
        }
        #pragma unroll
        for (int k = 0; k < 15; k++)
            s[OFF_B0 + (27 + k) * S + p] = s[OFF_B1 + (1 + k) * S + p];
        out[gn] = s[OFF_B1 + 0 * S + p];               // sigma
    }
    __syncthreads();

    // ---- color net ----
    gemmC<42, true>(s + OFF_B0, s + OFF_B1, OFF_CW0, warp, lane);
    __syncthreads();
    gemmC<64, true>(s + OFF_B1, s + OFF_B0, OFF_CW1, warp, lane);
    __syncthreads();

    // ---- final 64 -> 3 + sigmoid ----
    if (tid < BP) {
        const int p = tid;
        const int gn = gbase + p;
        float r0 = 0.f, r1 = 0.f, r2 = 0.f;
        #pragma unroll 8
        for (int i = 0; i < 64; i++) {
            float xv = s[OFF_B0 + i * S + p];
            r0 = fmaf(xv, c_w[OFF_CW2 + i * 3 + 0], r0);
            r1 = fmaf(xv, c_w[OFF_CW2 + i * 3 + 1], r1);
            r2 = fmaf(xv, c_w[OFF_CW2 + i * 3 + 2], r2);
        }
        out[(size_t)NPTS + (size_t)gn * 3 + 0] = 1.f / (1.f + __expf(-r0));
        out[(size_t)NPTS + (size_t)gn * 3 + 1] = 1.f / (1.f + __expf(-r1));
        out[(size_t)NPTS + (size_t)gn * 3 + 2] = 1.f / (1.f + __expf(-r2));
    }
}

// ---------------------------------------------------------------------------
extern "C" void kernel_launch(void* const* d_in, const int* in_sizes, int n_in,
                              void* d_out, int out_size)
{
    const float* xyzt  = (const float*)d_in[0];
    const float* dirs  = (const float*)d_in[1];
    const float* table = (const float*)d_in[2];

    cudaMemcpyToSymbolAsync(c_w, d_in[3], 2048 * 4, OFF_SW0 * 4,
                            cudaMemcpyDeviceToDevice);
    cudaMemcpyToSymbolAsync(c_w, d_in[4], 4096 * 4, OFF_SW1 * 4,
                            cudaMemcpyDeviceToDevice);
    cudaMemcpyToSymbolAsync(c_w, d_in[5], 1024 * 4, OFF_SW2 * 4,
                            cudaMemcpyDeviceToDevice);
    cudaMemcpyToSymbolAsync(c_w, d_in[6], 2688 * 4, OFF_CW0 * 4,
                            cudaMemcpyDeviceToDevice);
    cudaMemcpyToSymbolAsync(c_w, d_in[7], 4096 * 4, OFF_CW1 * 4,
                            cudaMemcpyDeviceToDevice);
    cudaMemcpyToSymbolAsync(c_w, d_in[8], 192 * 4, OFF_CW2 * 4,
                            cudaMemcpyDeviceToDevice);

    cudaFuncSetAttribute(fused_kernel, cudaFuncAttributeMaxDynamicSharedMemorySize,
                         SMEM_BYTES);

    fused_kernel<<<NPTS / BP, 256, SMEM_BYTES>>>(xyzt, dirs, table, (float*)d_out);
}